// round 11
// baseline (speedup 1.0000x reference)
#include <cuda_runtime.h>
#include <math.h>

#define BB 4
#define DD 64
#define NV (DD*DD*DD)        // 262144 voxels per batch (2^18)
#define TOT (BB*NV)          // 1048576
#define NP 512               // points per batch
#define NCOL (TOT/64)        // 16384 z-columns

// -------- scratch (device globals: no allocations allowed) --------
__device__ double g_part[256];
__device__ float  g_mean;
__device__ int    g_parent[TOT];                 // -1 = background
__device__ unsigned long long g_colmask[NCOL];   // foreground bits per z-column
__device__ int    g_num[BB];                     // component count per batch

// -------- 1) deterministic mean: two fixed-order tree reductions ----------
__global__ void k_reduce1(const float* __restrict__ x) {
    __shared__ double sh[256];
    const int t = threadIdx.x, bk = blockIdx.x;
    const int CH4 = (TOT / 256) / 4;       // 1024 float4 per block
    const float4* __restrict__ x4 = (const float4*)x + bk * CH4;
    double s = 0.0;
    for (int i = t; i < CH4; i += 256) {
        float4 v = x4[i];
        s += ((double)v.x + (double)v.y) + ((double)v.z + (double)v.w);
    }
    sh[t] = s; __syncthreads();
    for (int o = 128; o > 0; o >>= 1) { if (t < o) sh[t] += sh[t + o]; __syncthreads(); }
    if (t == 0) g_part[bk] = sh[0];
}

__global__ void k_reduce2() {
    __shared__ double sh[256];
    const int t = threadIdx.x;
    sh[t] = g_part[t]; __syncthreads();
    for (int o = 128; o > 0; o >>= 1) { if (t < o) sh[t] += sh[t + o]; __syncthreads(); }
    if (t == 0) g_mean = (float)(sh[0] / (double)TOT);
    if (t < BB) g_num[t] = 0;              // re-zero every replay
}

// -------- 2) init: z-run-start labels + column masks (no atomics) ----------
// block = 256 threads = 4 columns x 64 z
__global__ void k_init(const float* __restrict__ x) {
    __shared__ unsigned int shm[8];        // 8 half-column ballots
    const int t = threadIdx.x;
    const int z = t & 63;
    const int col = blockIdx.x * 4 + (t >> 6);
    const int i = (col << 6) + z;

    const bool fg = (x[i] > g_mean);
    const unsigned int b32 = __ballot_sync(0xFFFFFFFFu, fg);
    if ((t & 31) == 0) shm[t >> 5] = b32;
    __syncthreads();

    const int c = t >> 6;
    const unsigned long long m =
        (unsigned long long)shm[c * 2] |
        ((unsigned long long)shm[c * 2 + 1] << 32);

    if (fg) {
        const unsigned long long below =
            (z == 0) ? 0ull : (~m & ((1ull << z) - 1ull));
        const int start = below ? (64 - __clzll(below)) : 0;
        g_parent[i] = (col << 6) + start;
    } else {
        g_parent[i] = -1;
    }

    if (z == 0) g_colmask[col] = m;
}

// -------- global union-find: read-only find, min-link union (NO counting) ----
__device__ __forceinline__ int uf_find(int i) {
    int p = g_parent[i];
    while (p != i) { i = p; p = g_parent[i]; }
    return i;
}

// link two roots (with retry); roots only ever decrease
__device__ __forceinline__ void uf_link(int a, int b) {
    while (true) {
        if (a == b) return;
        if (a > b) { int t = a; a = b; b = t; }
        const int old = atomicMin(&g_parent[b], a);
        if (old == b) return;
        b = uf_find(old);
        a = uf_find(a);
    }
}

__device__ __forceinline__ void uf_unite(int a, int b) {
    uf_link(uf_find(a), uf_find(b));
}

// fused 4-way find: advance four independent chains concurrently (MLP=4)
__device__ __forceinline__ void uf_find4(int& w0, int& w1, int& w2, int& w3) {
    int p0 = g_parent[w0];
    int p1 = g_parent[w1];
    int p2 = g_parent[w2];
    int p3 = g_parent[w3];
    while ((p0 != w0) | (p1 != w1) | (p2 != w2) | (p3 != w3)) {
        w0 = p0; w1 = p1; w2 = p2; w3 = p3;
        p0 = g_parent[w0];
        p1 = g_parent[w1];
        p2 = g_parent[w2];
        p3 = g_parent[w3];
    }
}

// run start of z-run containing bit z of mask m (bit z must be set)
__device__ __forceinline__ int run_start(unsigned long long m, int z) {
    const unsigned long long below =
        (z == 0) ? 0ull : (~m & ((1ull << z) - 1ull));
    return below ? (64 - __clzll(below)) : 0;
}

// -------- 3) merge: one thread per voxel, BOTH -y and -x edges -------------
__global__ void k_merge() {
    const int i = blockIdx.x * blockDim.x + threadIdx.x;
    const int z = i & 63;
    const int col = i >> 6;
    const int y = col & 63;
    const int x = (col >> 6) & 63;

    const unsigned long long mA = __ldg(&g_colmask[col]);
    if (!((mA >> z) & 1ull)) return;       // background voxel: no edges

    // -y edge candidate
    int a1 = -1, b1 = -1;
    if (y > 0) {
        const unsigned long long mB = __ldg(&g_colmask[col - 1]);
        const unsigned long long ov = mA & mB;
        if (((ov >> z) & 1ull) && !(z > 0 && ((ov >> (z - 1)) & 1ull))) {
            a1 = (col << 6) + run_start(mA, z);
            b1 = ((col - 1) << 6) + run_start(mB, z);
        }
    }
    // -x edge candidate
    int a2 = -1, b2 = -1;
    if (x > 0) {
        const unsigned long long mC = __ldg(&g_colmask[col - 64]);
        const unsigned long long ov = mA & mC;
        if (((ov >> z) & 1ull) && !(z > 0 && ((ov >> (z - 1)) & 1ull))) {
            a2 = (col << 6) + run_start(mA, z);
            b2 = ((col - 64) << 6) + run_start(mC, z);
        }
    }

    if (a1 >= 0 && a2 >= 0) {              // both edges: overlap the 4 finds
        uf_find4(a1, b1, a2, b2);
        uf_link(a1, b1);
        uf_link(a2, b2);
    } else if (a1 >= 0) {
        uf_unite(a1, b1);
    } else if (a2 >= 0) {
        uf_unite(a2, b2);
    }
}

// -------- 4) count roots: block-aggregated (one atomic per 256 voxels) -----
__global__ void k_count() {
    const int i = blockIdx.x * blockDim.x + threadIdx.x;
    const int isroot = (g_parent[i] == i) ? 1 : 0;
    const int nblk = __syncthreads_count(isroot);
    if (threadIdx.x == 0 && nblk)
        atomicAdd(&g_num[i >> 18], nblk);  // block spans one batch segment
}

// -------- 5) fused point lookup + per-batch RMS (O(P^2) in shared) --------
__global__ void k_rms(const float* __restrict__ pts, float* __restrict__ out) {
    __shared__ int sh[NP];
    __shared__ int s_h0, s_sq, s_nc;
    const int b = blockIdx.x, t = threadIdx.x;

    const float* p = pts + (b * NP + t) * 3;
    const int s0 = (int)p[0];              // pts in [0, 64-1e-3): trunc == floor
    const int s1 = (int)p[1];
    const int s2 = (int)p[2];
    const int flat = (b << 18) + (s0 << 12) + (s1 << 6) + s2;
    const int pr = g_parent[flat];
    const int h = (pr >= 0) ? (uf_find(flat) + 1) : 0;

    sh[t] = h;
    if (t == 0) { s_h0 = 0; s_sq = 0; s_nc = 0; }
    __syncthreads();

    int cnt = 0, first = -1;
    #pragma unroll 8
    for (int j = 0; j < NP; j++) {
        if (sh[j] == h) { if (cnt == 0) first = j; cnt++; }
    }
    if (h == 0) {
        atomicAdd(&s_h0, 1);
    } else if (first == t) {               // representative of a hit component
        const int d = cnt - 1;
        atomicAdd(&s_sq, d * d);           // (1-cnt)^2, exact in int
        atomicAdd(&s_nc, 1);
    }
    __syncthreads();
    if (t == 0) {
        const float num = (float)g_num[b];
        const float sq = (float)s_h0 * (float)s_h0
                       + (float)s_sq
                       + (num - (float)s_nc);   // unhit components
        out[b] = sqrtf(sq / (num + 1.0f));
    }
}

// -------- launcher ----------
extern "C" void kernel_launch(void* const* d_in, const int* in_sizes, int n_in,
                              void* d_out, int out_size) {
    const float* logits = (const float*)d_in[0];
    const float* pts    = (const float*)d_in[1];
    if (n_in >= 2 && in_sizes[0] != TOT) {   // defensive input-order check
        logits = (const float*)d_in[1];
        pts    = (const float*)d_in[0];
    }
    k_reduce1<<<256, 256>>>(logits);
    k_reduce2<<<1, 256>>>();
    k_init<<<TOT / 256, 256>>>(logits);
    k_merge<<<TOT / 256, 256>>>();
    k_count<<<TOT / 256, 256>>>();
    k_rms<<<BB, NP>>>(pts, (float*)d_out);
}

// round 12
// speedup vs baseline: 1.1580x; 1.1580x over previous
#include <cuda_runtime.h>
#include <math.h>

#define BB 4
#define DD 64
#define NV (DD*DD*DD)        // 262144 voxels per batch (2^18)
#define TOT (BB*NV)          // 1048576
#define NP 512               // points per batch
#define NCOL (TOT/64)        // 16384 z-columns

// -------- scratch (device globals: no allocations allowed) --------
__device__ double g_part[256];
__device__ unsigned int g_arrived;               // last-block counter (self-resetting)
__device__ float  g_mean;
__device__ int    g_parent[TOT];                 // -1 = background
__device__ unsigned long long g_colmask[NCOL];   // foreground bits per z-column
__device__ int    g_num[BB];                     // component count per batch

// -------- 1) deterministic mean: single kernel, last-block finalize --------
__global__ void k_reduce(const float* __restrict__ x) {
    __shared__ double sh[256];
    __shared__ bool is_last;
    const int t = threadIdx.x, bk = blockIdx.x;
    const int CH4 = (TOT / 256) / 4;       // 1024 float4 per block
    const float4* __restrict__ x4 = (const float4*)x + bk * CH4;
    double s = 0.0;
    for (int i = t; i < CH4; i += 256) {
        float4 v = x4[i];
        s += ((double)v.x + (double)v.y) + ((double)v.z + (double)v.w);
    }
    sh[t] = s; __syncthreads();
    for (int o = 128; o > 0; o >>= 1) { if (t < o) sh[t] += sh[t + o]; __syncthreads(); }
    if (t == 0) {
        g_part[bk] = sh[0];
        __threadfence();
        is_last = (atomicAdd(&g_arrived, 1u) == 255u);
    }
    __syncthreads();
    if (!is_last) return;

    // last block: fixed-order final reduction (deterministic)
    sh[t] = g_part[t]; __syncthreads();
    for (int o = 128; o > 0; o >>= 1) { if (t < o) sh[t] += sh[t + o]; __syncthreads(); }
    if (t == 0) {
        g_mean = (float)(sh[0] / (double)TOT);
        g_arrived = 0;                     // reset for next graph replay
        __threadfence();
    }
    if (t < BB) g_num[t] = 0;              // re-zero every replay
}

// -------- 2) init: z-run-start labels + column masks + run-count seed ------
// block = 256 threads = 4 columns x 64 z (batch-pure)
__global__ void k_init(const float* __restrict__ x) {
    __shared__ unsigned int shm[8];        // 8 half-column ballots
    __shared__ int s_runs;
    const int t = threadIdx.x;
    const int z = t & 63;
    const int col = blockIdx.x * 4 + (t >> 6);
    const int i = (col << 6) + z;

    if (t == 0) s_runs = 0;
    const bool fg = (x[i] > g_mean);
    const unsigned int b32 = __ballot_sync(0xFFFFFFFFu, fg);
    if ((t & 31) == 0) shm[t >> 5] = b32;
    __syncthreads();

    const int c = t >> 6;
    const unsigned long long m =
        (unsigned long long)shm[c * 2] |
        ((unsigned long long)shm[c * 2 + 1] << 32);

    if (fg) {
        const unsigned long long below =
            (z == 0) ? 0ull : (~m & ((1ull << z) - 1ull));
        const int start = below ? (64 - __clzll(below)) : 0;
        g_parent[i] = (col << 6) + start;
    } else {
        g_parent[i] = -1;
    }

    if (z == 0) {
        g_colmask[col] = m;
        const int nruns = __popcll(m & ~(m << 1));
        if (nruns) atomicAdd(&s_runs, nruns);
    }
    __syncthreads();
    if (t == 0 && s_runs)
        atomicAdd(&g_num[col >> 12], s_runs);   // one global atomic per block
}

// -------- global union-find: read-only find, min-link union ----------------
__device__ __forceinline__ int uf_find(int i) {
    int p = g_parent[i];
    while (p != i) { i = p; p = g_parent[i]; }
    return i;
}

// returns 1 if this call demoted a root (happens at most once per call)
__device__ __forceinline__ int uf_unite(int a, int b) {
    while (true) {
        a = uf_find(a);
        b = uf_find(b);
        if (a == b) return 0;
        if (a > b) { int t = a; a = b; b = t; }
        const int old = atomicMin(&g_parent[b], a);
        if (old == b) return 1;            // b was a root; demoted exactly once
        b = old;
    }
}

// run start of z-run containing bit z of mask m (bit z must be set)
__device__ __forceinline__ int run_start(unsigned long long m, int z) {
    const unsigned long long below =
        (z == 0) ? 0ull : (~m & ((1ull << z) - 1ull));
    return below ? (64 - __clzll(below)) : 0;
}

// -------- 3) merge: one thread per (voxel, x/y-dir); fused demote count ----
// blocks are batch-pure: i-range of 256 consecutive voxels, single dir.
__global__ void k_merge() {
    const int t = blockIdx.x * blockDim.x + threadIdx.x;
    const int i = t & (TOT - 1);
    const int dir = t >> 20;               // 0: -y, 1: -x
    const int z = i & 63;
    const int col = i >> 6;
    const int y = col & 63;
    const int x = (col >> 6) & 63;

    int demoted = 0;
    int nbr = -1;
    if (dir == 0) { if (y > 0) nbr = col - 1;  }
    else          { if (x > 0) nbr = col - 64; }

    if (nbr >= 0) {
        const unsigned long long mA = __ldg(&g_colmask[col]);
        const unsigned long long mB = __ldg(&g_colmask[nbr]);
        const unsigned long long ov = mA & mB;
        const bool edge = ((ov >> z) & 1ull) &&
                          !(z > 0 && ((ov >> (z - 1)) & 1ull));   // overlap-run start
        if (edge) {
            const int a = (col << 6) + run_start(mA, z);
            const int b = (nbr << 6) + run_start(mB, z);
            demoted = uf_unite(a, b);
        }
    }

    const int nblk = __syncthreads_count(demoted);
    if (threadIdx.x == 0 && nblk)
        atomicSub(&g_num[i >> 18], nblk);  // num = n_runs - n_demotions
}

// -------- 4) fused point lookup + per-batch RMS (O(P^2) in shared) --------
__global__ void k_rms(const float* __restrict__ pts, float* __restrict__ out) {
    __shared__ int sh[NP];
    __shared__ int s_h0, s_sq, s_nc;
    const int b = blockIdx.x, t = threadIdx.x;

    const float* p = pts + (b * NP + t) * 3;
    const int s0 = (int)p[0];              // pts in [0, 64-1e-3): trunc == floor
    const int s1 = (int)p[1];
    const int s2 = (int)p[2];
    const int flat = (b << 18) + (s0 << 12) + (s1 << 6) + s2;
    const int pr = g_parent[flat];
    const int h = (pr >= 0) ? (uf_find(flat) + 1) : 0;

    sh[t] = h;
    if (t == 0) { s_h0 = 0; s_sq = 0; s_nc = 0; }
    __syncthreads();

    int cnt = 0, first = -1;
    #pragma unroll 8
    for (int j = 0; j < NP; j++) {
        if (sh[j] == h) { if (cnt == 0) first = j; cnt++; }
    }
    if (h == 0) {
        atomicAdd(&s_h0, 1);
    } else if (first == t) {               // representative of a hit component
        const int d = cnt - 1;
        atomicAdd(&s_sq, d * d);           // (1-cnt)^2, exact in int
        atomicAdd(&s_nc, 1);
    }
    __syncthreads();
    if (t == 0) {
        const float num = (float)g_num[b];
        const float sq = (float)s_h0 * (float)s_h0
                       + (float)s_sq
                       + (num - (float)s_nc);   // unhit components
        out[b] = sqrtf(sq / (num + 1.0f));
    }
}

// -------- launcher ----------
extern "C" void kernel_launch(void* const* d_in, const int* in_sizes, int n_in,
                              void* d_out, int out_size) {
    const float* logits = (const float*)d_in[0];
    const float* pts    = (const float*)d_in[1];
    if (n_in >= 2 && in_sizes[0] != TOT) {   // defensive input-order check
        logits = (const float*)d_in[1];
        pts    = (const float*)d_in[0];
    }
    k_reduce<<<256, 256>>>(logits);
    k_init<<<TOT / 256, 256>>>(logits);
    k_merge<<<(2 * TOT) / 256, 256>>>();
    k_rms<<<BB, NP>>>(pts, (float*)d_out);
}

// round 13
// speedup vs baseline: 1.2886x; 1.1127x over previous
#include <cuda_runtime.h>
#include <math.h>

#define BB 4
#define DD 64
#define NV (DD*DD*DD)        // 262144 voxels per batch (2^18)
#define TOT (BB*NV)          // 1048576
#define NP 512               // points per batch
#define NCOL (TOT/64)        // 16384 z-columns
#define HSZ 1024             // hash slots (>= 2*NP)

// -------- scratch (device globals: no allocations allowed) --------
__device__ double g_part[256];
__device__ unsigned int g_arrived;               // last-block counter (self-resetting)
__device__ float  g_mean;
__device__ int    g_parent[TOT];                 // -1 = background
__device__ unsigned long long g_colmask[NCOL];   // foreground bits per z-column
__device__ int    g_num[BB];                     // component count per batch

// -------- 1) deterministic mean: single kernel, last-block finalize --------
__global__ void k_reduce(const float* __restrict__ x) {
    __shared__ double sh[256];
    __shared__ bool is_last;
    const int t = threadIdx.x, bk = blockIdx.x;
    const int CH4 = (TOT / 256) / 4;       // 1024 float4 per block
    const float4* __restrict__ x4 = (const float4*)x + bk * CH4;
    double s = 0.0;
    for (int i = t; i < CH4; i += 256) {
        float4 v = x4[i];
        s += ((double)v.x + (double)v.y) + ((double)v.z + (double)v.w);
    }
    sh[t] = s; __syncthreads();
    for (int o = 128; o > 0; o >>= 1) { if (t < o) sh[t] += sh[t + o]; __syncthreads(); }
    if (t == 0) {
        g_part[bk] = sh[0];
        __threadfence();
        is_last = (atomicAdd(&g_arrived, 1u) == 255u);
    }
    __syncthreads();
    if (!is_last) return;

    // last block: fixed-order final reduction (deterministic)
    sh[t] = g_part[t]; __syncthreads();
    for (int o = 128; o > 0; o >>= 1) { if (t < o) sh[t] += sh[t + o]; __syncthreads(); }
    if (t == 0) {
        g_mean = (float)(sh[0] / (double)TOT);
        g_arrived = 0;                     // reset for next graph replay
        __threadfence();
    }
    if (t < BB) g_num[t] = 0;              // re-zero every replay
}

// -------- 2) init: z-run-start labels + column masks + run-count seed ------
// block = 256 threads = 4 columns x 64 z (batch-pure)
__global__ void k_init(const float* __restrict__ x) {
    __shared__ unsigned int shm[8];        // 8 half-column ballots
    __shared__ int s_runs;
    const int t = threadIdx.x;
    const int z = t & 63;
    const int col = blockIdx.x * 4 + (t >> 6);
    const int i = (col << 6) + z;

    if (t == 0) s_runs = 0;
    const bool fg = (x[i] > g_mean);
    const unsigned int b32 = __ballot_sync(0xFFFFFFFFu, fg);
    if ((t & 31) == 0) shm[t >> 5] = b32;
    __syncthreads();

    const int c = t >> 6;
    const unsigned long long m =
        (unsigned long long)shm[c * 2] |
        ((unsigned long long)shm[c * 2 + 1] << 32);

    if (fg) {
        const unsigned long long below =
            (z == 0) ? 0ull : (~m & ((1ull << z) - 1ull));
        const int start = below ? (64 - __clzll(below)) : 0;
        g_parent[i] = (col << 6) + start;
    } else {
        g_parent[i] = -1;
    }

    if (z == 0) {
        g_colmask[col] = m;
        const int nruns = __popcll(m & ~(m << 1));
        if (nruns) atomicAdd(&s_runs, nruns);
    }
    __syncthreads();
    if (t == 0 && s_runs)
        atomicAdd(&g_num[col >> 12], s_runs);   // one global atomic per block
}

// -------- global union-find: read-only find, min-link union ----------------
__device__ __forceinline__ int uf_find(int i) {
    int p = g_parent[i];
    while (p != i) { i = p; p = g_parent[i]; }
    return i;
}

// returns 1 if this call demoted a root (happens at most once per call)
__device__ __forceinline__ int uf_unite(int a, int b) {
    while (true) {
        a = uf_find(a);
        b = uf_find(b);
        if (a == b) return 0;
        if (a > b) { int t = a; a = b; b = t; }
        const int old = atomicMin(&g_parent[b], a);
        if (old == b) return 1;            // b was a root; demoted exactly once
        b = old;
    }
}

// run start of z-run containing bit z of mask m (bit z must be set)
__device__ __forceinline__ int run_start(unsigned long long m, int z) {
    const unsigned long long below =
        (z == 0) ? 0ull : (~m & ((1ull << z) - 1ull));
    return below ? (64 - __clzll(below)) : 0;
}

// -------- 3) merge: one thread per (voxel, x/y-dir); fused demote count ----
// blocks are batch-pure: i-range of 256 consecutive voxels, single dir.
__global__ void k_merge() {
    const int t = blockIdx.x * blockDim.x + threadIdx.x;
    const int i = t & (TOT - 1);
    const int dir = t >> 20;               // 0: -y, 1: -x
    const int z = i & 63;
    const int col = i >> 6;
    const int y = col & 63;
    const int x = (col >> 6) & 63;

    int demoted = 0;
    int nbr = -1;
    if (dir == 0) { if (y > 0) nbr = col - 1;  }
    else          { if (x > 0) nbr = col - 64; }

    if (nbr >= 0) {
        const unsigned long long mA = __ldg(&g_colmask[col]);
        const unsigned long long mB = __ldg(&g_colmask[nbr]);
        const unsigned long long ov = mA & mB;
        const bool edge = ((ov >> z) & 1ull) &&
                          !(z > 0 && ((ov >> (z - 1)) & 1ull));   // overlap-run start
        if (edge) {
            const int a = (col << 6) + run_start(mA, z);
            const int b = (nbr << 6) + run_start(mB, z);
            demoted = uf_unite(a, b);
        }
    }

    const int nblk = __syncthreads_count(demoted);
    if (threadIdx.x == 0 && nblk)
        atomicSub(&g_num[i >> 18], nblk);  // num = n_runs - n_demotions
}

// -------- 4) fused point lookup + per-batch RMS (O(P) hash count) ----------
__global__ void k_rms(const float* __restrict__ pts, float* __restrict__ out) {
    __shared__ int keys[HSZ];
    __shared__ int cnts[HSZ];
    __shared__ int s_sq, s_nc;
    const int b = blockIdx.x, t = threadIdx.x;

    // init hash table (each thread clears 2 slots)
    keys[t] = -1;           cnts[t] = 0;
    keys[t + NP] = -1;      cnts[t + NP] = 0;
    if (t == 0) { s_sq = 0; s_nc = 0; }

    const float* p = pts + (b * NP + t) * 3;
    const int s0 = (int)p[0];              // pts in [0, 64-1e-3): trunc == floor
    const int s1 = (int)p[1];
    const int s2 = (int)p[2];
    const int flat = (b << 18) + (s0 << 12) + (s1 << 6) + s2;
    const int pr = g_parent[flat];
    const int h = (pr >= 0) ? (uf_find(flat) + 1) : 0;
    __syncthreads();

    // insert into hash table; remember if we own the slot (first inserter)
    int my_slot = -1;
    if (h > 0) {
        unsigned int slot = ((unsigned int)h * 2654435761u) & (HSZ - 1);
        while (true) {
            const int k = atomicCAS(&keys[slot], -1, h);
            if (k == -1 || k == h) {
                atomicAdd(&cnts[slot], 1);
                if (k == -1) my_slot = (int)slot;
                break;
            }
            slot = (slot + 1) & (HSZ - 1);
        }
    }
    const int hits0 = __syncthreads_count(h == 0);   // also orders table writes

    // slot owners contribute per-component terms
    if (my_slot >= 0) {
        const int d = cnts[my_slot] - 1;
        atomicAdd(&s_sq, d * d);           // (1-cnt)^2, exact in int
        atomicAdd(&s_nc, 1);
    }
    __syncthreads();

    if (t == 0) {
        const float num = (float)g_num[b];
        const float sq = (float)hits0 * (float)hits0
                       + (float)s_sq
                       + (num - (float)s_nc);   // unhit components
        out[b] = sqrtf(sq / (num + 1.0f));
    }
}

// -------- launcher ----------
extern "C" void kernel_launch(void* const* d_in, const int* in_sizes, int n_in,
                              void* d_out, int out_size) {
    const float* logits = (const float*)d_in[0];
    const float* pts    = (const float*)d_in[1];
    if (n_in >= 2 && in_sizes[0] != TOT) {   // defensive input-order check
        logits = (const float*)d_in[1];
        pts    = (const float*)d_in[0];
    }
    k_reduce<<<256, 256>>>(logits);
    k_init<<<TOT / 256, 256>>>(logits);
    k_merge<<<(2 * TOT) / 256, 256>>>();
    k_rms<<<BB, NP>>>(pts, (float*)d_out);
}